// round 8
// baseline (speedup 1.0000x reference)
#include <cuda_runtime.h>

#define Bsz 64
#define Dd  512
#define Ll  8192
#define NLn 1000

typedef unsigned long long ull;

// Intermediates (device globals; allocations forbidden).
// Never passed as host-side kernel args — kernels reference them directly.
__device__ __align__(16) float g_ye0 [Bsz*Dd];
__device__ __align__(16) float g_ye1 [Bsz*Dd];
__device__ __align__(16) float g_ye2 [Bsz*Dd];
__device__ __align__(16) float g_zz1 [Bsz*Dd];
__device__ __align__(16) float g_zz2 [Bsz*Dd];
__device__ __align__(16) float g_s_pad[Bsz*32];   // s[b] at b*32 (sector-spread atomics)

__device__ __forceinline__ void cp_async16(void* dst, const void* src) {
    unsigned s = (unsigned)__cvta_generic_to_shared(dst);
    asm volatile("cp.async.cg.shared.global [%0], [%1], 16;" :: "r"(s), "l"(src) : "memory");
}
__device__ __forceinline__ ull pack2(float lo, float hi) {
    ull r; asm("mov.b64 %0, {%1, %2};" : "=l"(r) : "f"(lo), "f"(hi)); return r;
}
__device__ __forceinline__ void unpack2(float& lo, float& hi, ull v) {
    asm("mov.b64 {%0, %1}, %2;" : "=f"(lo), "=f"(hi) : "l"(v));
}
__device__ __forceinline__ void ffma2(ull& d, ull a, ull b) {
    asm("fma.rn.f32x2 %0, %1, %2, %0;" : "+l"(d) : "l"(a), "l"(b));
}
__device__ __forceinline__ void red4(float* p, float v0, float v1, float v2, float v3) {
    asm volatile("red.global.add.v4.f32 [%0], {%1,%2,%3,%4};"
                 :: "l"(p), "f"(v0), "f"(v1), "f"(v2), "f"(v3) : "memory");
}

// ---------------------------------------------------------------------------
// K1: ye0 gather, stage-1 residual inits, zero stage-2 accumulators + s.
// ---------------------------------------------------------------------------
__global__ void k_prep(const float* __restrict__ z, const int* __restrict__ y,
                       const float* __restrict__ W_yemb, const float* __restrict__ b_yemb,
                       const float* __restrict__ by1, const float* __restrict__ bz1) {
    int b = blockIdx.x;
    int e = blockIdx.y * 128 + threadIdx.x;
    int yb = __ldg(y + b);
    float v  = __ldg(W_yemb + e*NLn + yb) + b_yemb[e];
    float zv = z[b*Dd + e];
    g_ye0[b*Dd + e] = v;
    g_ye1[b*Dd + e] = v  + by1[e];
    g_zz1[b*Dd + e] = zv + bz1[e];
    g_ye2[b*Dd + e] = 0.f;
    g_zz2[b*Dd + e] = 0.f;
    if (blockIdx.y == 0 && threadIdx.x == 0) g_s_pad[b*32] = 0.f;
}

// ---------------------------------------------------------------------------
// Small residual GEMM (unchanged from passing R5/R6 kernel).
// ---------------------------------------------------------------------------
template<int STAGE>
__global__ void __launch_bounds__(256) k_small(const float* __restrict__ z,
                                               const float* __restrict__ Wy,
                                               const float* __restrict__ Wz,
                                               const float* __restrict__ b2y,
                                               const float* __restrict__ b2z,
                                               const float* __restrict__ w_proj) {
    __shared__ float sA[64*68];   // [b][k] pad 68 (broadcast-read conflict-free)
    __shared__ float sW[64*32];   // [k][e] transposed
    const float* A; const float* W; const float* b2; float* C;
    if (STAGE == 1) {
        if (blockIdx.y == 0) { A = g_ye0; W = Wy; b2 = nullptr; C = g_ye1; }
        else                 { A = z;     W = Wz; b2 = nullptr; C = g_zz1; }
    } else {
        if (blockIdx.y == 0) { A = g_ye1; W = Wy; b2 = b2y; C = g_ye2; }
        else                 { A = g_zz1; W = Wz; b2 = b2z; C = g_zz2; }
    }
    const int t  = threadIdx.x;
    const int e0 = (blockIdx.x & 15) * 32;
    const int k0 = (blockIdx.x >> 4) * 64;

    #pragma unroll
    for (int r = 0; r < 4; r++) {
        int id = t + 256*r;              // 0..1023
        int b = id >> 4, k4 = id & 15;
        cp_async16(&sA[b*68 + 4*k4], A + b*Dd + k0 + 4*k4);
    }
    asm volatile("cp.async.commit_group;" ::: "memory");
    float4 wv[2]; int we[2], wk[2];
    #pragma unroll
    for (int r = 0; r < 2; r++) {
        int id = t + 256*r;              // 0..511
        we[r] = id >> 4; wk[r] = id & 15;
        wv[r] = *(const float4*)(W + (e0 + we[r])*Dd + k0 + 4*wk[r]);
    }
    #pragma unroll
    for (int r = 0; r < 2; r++) {
        sW[(4*wk[r] + 0)*32 + we[r]] = wv[r].x;
        sW[(4*wk[r] + 1)*32 + we[r]] = wv[r].y;
        sW[(4*wk[r] + 2)*32 + we[r]] = wv[r].z;
        sW[(4*wk[r] + 3)*32 + we[r]] = wv[r].w;
    }
    asm volatile("cp.async.wait_group 0;" ::: "memory");
    __syncthreads();

    const int b  = t >> 2;     // 0..63
    const int eg = t & 3;      // e-octet: e0 + eg*8 .. +7
    ull acc[4] = {0, 0, 0, 0};

    #pragma unroll 8
    for (int k = 0; k < 64; k++) {
        float a = sA[b*68 + k];
        ull ap = pack2(a, a);
        ulonglong2 wA = *(const ulonglong2*)&sW[k*32 + eg*8];
        ulonglong2 wB = *(const ulonglong2*)&sW[k*32 + eg*8 + 4];
        ffma2(acc[0], ap, wA.x);
        ffma2(acc[1], ap, wA.y);
        ffma2(acc[2], ap, wB.x);
        ffma2(acc[3], ap, wB.y);
    }

    float v[8];
    unpack2(v[0], v[1], acc[0]);
    unpack2(v[2], v[3], acc[1]);
    unpack2(v[4], v[5], acc[2]);
    unpack2(v[6], v[7], acc[3]);
    const int eo = e0 + eg*8;
    if (STAGE == 2 && k0 == 0) {
        float4 p0 = *(const float4*)&A[b*Dd + eo];
        float4 p1 = *(const float4*)&A[b*Dd + eo + 4];
        float4 q0 = *(const float4*)&b2[eo];
        float4 q1 = *(const float4*)&b2[eo + 4];
        v[0] += p0.x + q0.x; v[1] += p0.y + q0.y;
        v[2] += p0.z + q0.z; v[3] += p0.w + q0.w;
        v[4] += p1.x + q1.x; v[5] += p1.y + q1.y;
        v[6] += p1.z + q1.z; v[7] += p1.w + q1.w;
    }
    red4(&C[b*Dd + eo],     v[0], v[1], v[2], v[3]);
    red4(&C[b*Dd + eo + 4], v[4], v[5], v[6], v[7]);

    if (STAGE == 2 && blockIdx.y == 0) {
        float4 wp0 = *(const float4*)&w_proj[eo];
        float4 wp1 = *(const float4*)&w_proj[eo + 4];
        float sp = v[0]*wp0.x + v[1]*wp0.y + v[2]*wp0.z + v[3]*wp0.w
                 + v[4]*wp1.x + v[5]*wp1.y + v[6]*wp1.z + v[7]*wp1.w;
        sp += __shfl_xor_sync(0xffffffffu, sp, 1);
        sp += __shfl_xor_sync(0xffffffffu, sp, 2);
        if (eg == 0) atomicAdd(&g_s_pad[b*32], sp);
    }
}

// ---------------------------------------------------------------------------
// K4: out[b,l] = s[b] * dot(zz2[b,:], W_zlat[l,:])
// K-paired FFMA2. CTA 32b x 32l, 128 threads, thread tile 4b x 2l (8 accs).
// grid (256 l-tiles, 2 b-halves) = 512 CTAs -> ~3.5 CTAs/SM co-resident
// (14 warps/SM) to hide LDS latency; smem 18KB/CTA.
// ---------------------------------------------------------------------------
#define KCH 32            // k per chunk
#define SSTR 36           // row stride in floats (32 + 4 pad, 16B-aligned)
__global__ void __launch_bounds__(128) k_big(const float* __restrict__ Wz,
                                             float* __restrict__ out) {
    __shared__ float sA[2][32*SSTR];   // [b][k] row-major (4608 B each)
    __shared__ float sW[2][32*SSTR];   // [l][k] row-major (4608 B each)
    const int t    = threadIdx.x;
    const int l0   = blockIdx.x * 32;
    const int b0   = blockIdx.y * 32;
    const int lgrp = t & 15;           // l = l0 + lgrp + 16j   (j=0,1)
    const int bgrp = t >> 4;           // b = b0 + 4*bgrp + i   (i=0..3)

    auto load = [&](int buf, int c) {
        #pragma unroll
        for (int r = 0; r < 2; r++) {
            int id  = t + 128*r;       // 0..255
            int row = id >> 3, k4 = id & 7;
            cp_async16(&sA[buf][row*SSTR + 4*k4], g_zz2 + (b0 + row)*Dd + c*KCH + 4*k4);
            cp_async16(&sW[buf][row*SSTR + 4*k4], Wz + (l0 + row)*Dd + c*KCH + 4*k4);
        }
        asm volatile("cp.async.commit_group;" ::: "memory");
    };

    ull acc[4][2];
    #pragma unroll
    for (int i = 0; i < 4; i++) { acc[i][0] = 0; acc[i][1] = 0; }

    load(0, 0);
    #pragma unroll 1
    for (int c = 0; c < 16; c++) {
        const int cur = c & 1;
        asm volatile("cp.async.wait_group 0;" ::: "memory");  // chunk c arrived
        __syncthreads();               // all arrived; prior reads of other buf done
        if (c < 15) load(cur ^ 1, c + 1);   // prefetch overlaps compute
        const float* Ab = sA[cur];
        const float* Wb = sW[cur];
        #pragma unroll
        for (int kk = 0; kk < KCH/4; kk++) {
            ulonglong2 w0 = *(const ulonglong2*)&Wb[lgrp*SSTR + 4*kk];
            ulonglong2 w1 = *(const ulonglong2*)&Wb[(lgrp + 16)*SSTR + 4*kk];
            #pragma unroll
            for (int i = 0; i < 4; i++) {
                ulonglong2 a = *(const ulonglong2*)&Ab[(4*bgrp + i)*SSTR + 4*kk];
                ffma2(acc[i][0], a.x, w0.x);
                ffma2(acc[i][0], a.y, w0.y);
                ffma2(acc[i][1], a.x, w1.x);
                ffma2(acc[i][1], a.y, w1.y);
            }
        }
    }

    // reduce k-pairs, scale by s[b], store
    #pragma unroll
    for (int i = 0; i < 4; i++) {
        const int b = b0 + 4*bgrp + i;
        const float s = g_s_pad[b*32];
        #pragma unroll
        for (int j = 0; j < 2; j++) {
            float lo, hi;
            unpack2(lo, hi, acc[i][j]);
            out[b*Ll + l0 + lgrp + 16*j] = (lo + hi) * s;
        }
    }
}

extern "C" void kernel_launch(void* const* d_in, const int* in_sizes, int n_in,
                              void* d_out, int out_size) {
    const float* z      = (const float*)d_in[0];
    const int*   y      = (const int*)  d_in[1];
    const float* W_yemb = (const float*)d_in[2];
    const float* b_yemb = (const float*)d_in[3];
    const float* Wy1    = (const float*)d_in[4];
    const float* by1    = (const float*)d_in[5];
    const float* Wy2    = (const float*)d_in[6];
    const float* by2    = (const float*)d_in[7];
    const float* Wz1    = (const float*)d_in[8];
    const float* bz1    = (const float*)d_in[9];
    const float* Wz2    = (const float*)d_in[10];
    const float* bz2    = (const float*)d_in[11];
    const float* W_zlat = (const float*)d_in[12];
    const float* w_proj = (const float*)d_in[13];
    float* out = (float*)d_out;

    k_prep<<<dim3(Bsz, 4), 128>>>(z, y, W_yemb, b_yemb, by1, bz1);
    k_small<1><<<dim3(128, 2), 256>>>(z, Wy1, Wz1, nullptr, nullptr, nullptr);
    k_small<2><<<dim3(128, 2), 256>>>(z, Wy2, Wz2, by2, bz2, w_proj);
    k_big<<<dim3(Ll/32, 2), 128>>>(W_zlat, out);
}

// round 10
// speedup vs baseline: 1.2474x; 1.2474x over previous
#include <cuda_runtime.h>
#include <cstdint>

#define Bsz 64
#define Dd  512
#define Ll  8192
#define NLn 1000

typedef unsigned long long ull;

// Intermediates (device globals; allocations forbidden).
// Never passed as host-side kernel args — kernels reference them directly.
__device__ __align__(16) float g_ye0 [Bsz*Dd];
__device__ __align__(16) float g_ye1 [Bsz*Dd];
__device__ __align__(16) float g_ye2 [Bsz*Dd];
__device__ __align__(16) float g_zz1 [Bsz*Dd];
__device__ __align__(16) float g_zz2 [Bsz*Dd];
__device__ __align__(16) float g_s_pad[Bsz*32];   // s[b] at b*32

__device__ __forceinline__ void cp_async16(void* dst, const void* src) {
    unsigned s = (unsigned)__cvta_generic_to_shared(dst);
    asm volatile("cp.async.cg.shared.global [%0], [%1], 16;" :: "r"(s), "l"(src) : "memory");
}
__device__ __forceinline__ ull pack2(float lo, float hi) {
    ull r; asm("mov.b64 %0, {%1, %2};" : "=l"(r) : "f"(lo), "f"(hi)); return r;
}
__device__ __forceinline__ void unpack2(float& lo, float& hi, ull v) {
    asm("mov.b64 {%0, %1}, %2;" : "=f"(lo), "=f"(hi) : "l"(v));
}
__device__ __forceinline__ void ffma2(ull& d, ull a, ull b) {
    asm("fma.rn.f32x2 %0, %1, %2, %0;" : "+l"(d) : "l"(a), "l"(b));
}
__device__ __forceinline__ void red4(float* p, float v0, float v1, float v2, float v3) {
    asm volatile("red.global.add.v4.f32 [%0], {%1,%2,%3,%4};"
                 :: "l"(p), "f"(v0), "f"(v1), "f"(v2), "f"(v3) : "memory");
}

// ---------------------------------------------------------------------------
// K1: ye0 gather, stage-1 residual inits, zero stage-2 accumulators + s.
// ---------------------------------------------------------------------------
__global__ void k_prep(const float* __restrict__ z, const int* __restrict__ y,
                       const float* __restrict__ W_yemb, const float* __restrict__ b_yemb,
                       const float* __restrict__ by1, const float* __restrict__ bz1) {
    int b = blockIdx.x;
    int e = blockIdx.y * 128 + threadIdx.x;
    int yb = __ldg(y + b);
    float v  = __ldg(W_yemb + e*NLn + yb) + b_yemb[e];
    float zv = z[b*Dd + e];
    g_ye0[b*Dd + e] = v;
    g_ye1[b*Dd + e] = v  + by1[e];
    g_zz1[b*Dd + e] = zv + bz1[e];
    g_ye2[b*Dd + e] = 0.f;
    g_zz2[b*Dd + e] = 0.f;
    if (blockIdx.y == 0 && threadIdx.x == 0) g_s_pad[b*32] = 0.f;
}

// ---------------------------------------------------------------------------
// Small residual GEMM (unchanged from passing R5..R8 kernels).
// ---------------------------------------------------------------------------
template<int STAGE>
__global__ void __launch_bounds__(256) k_small(const float* __restrict__ z,
                                               const float* __restrict__ Wy,
                                               const float* __restrict__ Wz,
                                               const float* __restrict__ b2y,
                                               const float* __restrict__ b2z,
                                               const float* __restrict__ w_proj) {
    __shared__ float sA[64*68];
    __shared__ float sW[64*32];
    const float* A; const float* W; const float* b2; float* C;
    if (STAGE == 1) {
        if (blockIdx.y == 0) { A = g_ye0; W = Wy; b2 = nullptr; C = g_ye1; }
        else                 { A = z;     W = Wz; b2 = nullptr; C = g_zz1; }
    } else {
        if (blockIdx.y == 0) { A = g_ye1; W = Wy; b2 = b2y; C = g_ye2; }
        else                 { A = g_zz1; W = Wz; b2 = b2z; C = g_zz2; }
    }
    const int t  = threadIdx.x;
    const int e0 = (blockIdx.x & 15) * 32;
    const int k0 = (blockIdx.x >> 4) * 64;

    #pragma unroll
    for (int r = 0; r < 4; r++) {
        int id = t + 256*r;
        int b = id >> 4, k4 = id & 15;
        cp_async16(&sA[b*68 + 4*k4], A + b*Dd + k0 + 4*k4);
    }
    asm volatile("cp.async.commit_group;" ::: "memory");
    float4 wv[2]; int we[2], wk[2];
    #pragma unroll
    for (int r = 0; r < 2; r++) {
        int id = t + 256*r;
        we[r] = id >> 4; wk[r] = id & 15;
        wv[r] = *(const float4*)(W + (e0 + we[r])*Dd + k0 + 4*wk[r]);
    }
    #pragma unroll
    for (int r = 0; r < 2; r++) {
        sW[(4*wk[r] + 0)*32 + we[r]] = wv[r].x;
        sW[(4*wk[r] + 1)*32 + we[r]] = wv[r].y;
        sW[(4*wk[r] + 2)*32 + we[r]] = wv[r].z;
        sW[(4*wk[r] + 3)*32 + we[r]] = wv[r].w;
    }
    asm volatile("cp.async.wait_group 0;" ::: "memory");
    __syncthreads();

    const int b  = t >> 2;
    const int eg = t & 3;
    ull acc[4] = {0, 0, 0, 0};

    #pragma unroll 8
    for (int k = 0; k < 64; k++) {
        float a = sA[b*68 + k];
        ull ap = pack2(a, a);
        ulonglong2 wA = *(const ulonglong2*)&sW[k*32 + eg*8];
        ulonglong2 wB = *(const ulonglong2*)&sW[k*32 + eg*8 + 4];
        ffma2(acc[0], ap, wA.x);
        ffma2(acc[1], ap, wA.y);
        ffma2(acc[2], ap, wB.x);
        ffma2(acc[3], ap, wB.y);
    }

    float v[8];
    unpack2(v[0], v[1], acc[0]);
    unpack2(v[2], v[3], acc[1]);
    unpack2(v[4], v[5], acc[2]);
    unpack2(v[6], v[7], acc[3]);
    const int eo = e0 + eg*8;
    if (STAGE == 2 && k0 == 0) {
        float4 p0 = *(const float4*)&A[b*Dd + eo];
        float4 p1 = *(const float4*)&A[b*Dd + eo + 4];
        float4 q0 = *(const float4*)&b2[eo];
        float4 q1 = *(const float4*)&b2[eo + 4];
        v[0] += p0.x + q0.x; v[1] += p0.y + q0.y;
        v[2] += p0.z + q0.z; v[3] += p0.w + q0.w;
        v[4] += p1.x + q1.x; v[5] += p1.y + q1.y;
        v[6] += p1.z + q1.z; v[7] += p1.w + q1.w;
    }
    red4(&C[b*Dd + eo],     v[0], v[1], v[2], v[3]);
    red4(&C[b*Dd + eo + 4], v[4], v[5], v[6], v[7]);

    if (STAGE == 2 && blockIdx.y == 0) {
        float4 wp0 = *(const float4*)&w_proj[eo];
        float4 wp1 = *(const float4*)&w_proj[eo + 4];
        float sp = v[0]*wp0.x + v[1]*wp0.y + v[2]*wp0.z + v[3]*wp0.w
                 + v[4]*wp1.x + v[5]*wp1.y + v[6]*wp1.z + v[7]*wp1.w;
        sp += __shfl_xor_sync(0xffffffffu, sp, 1);
        sp += __shfl_xor_sync(0xffffffffu, sp, 2);
        if (eg == 0) atomicAdd(&g_s_pad[b*32], sp);
    }
}

// ---------------------------------------------------------------------------
// k_big_mma: out[b,l] = s[b] * dot(zz2[b,:], W_zlat[l,:]) via mma.sync bf16
// 3-pass split (AhWh + AhWl + AlWh), fp32 register accumulators.
// CTA 64b x 32l, 128 threads = 4 warps (2b x 2l), warp tile 32b x 16l
// (2 m16-atoms x 2 n8-atoms, m16n8k16). Grid 256.
// smem: bf16-pair uint32 tiles, row pitch 20 (16 data + 4 pad) ->
// fragment LDS.32 hits 32 distinct banks (20r mod 32 = stride-4 set, + t4).
// ---------------------------------------------------------------------------
#define PITCH 20
__device__ __forceinline__ uint32_t bf2(float lo, float hi) {
    uint32_t r; asm("cvt.rn.bf16x2.f32 %0, %1, %2;" : "=r"(r) : "f"(hi), "f"(lo)); return r;
}
__device__ __forceinline__ void cvt_hilo(float4 f, uint32_t& h0, uint32_t& h1,
                                         uint32_t& l0, uint32_t& l1) {
    h0 = bf2(f.x, f.y);
    h1 = bf2(f.z, f.w);
    float hx = __uint_as_float(h0 << 16), hy = __uint_as_float(h0 & 0xffff0000u);
    float hz = __uint_as_float(h1 << 16), hw = __uint_as_float(h1 & 0xffff0000u);
    l0 = bf2(f.x - hx, f.y - hy);
    l1 = bf2(f.z - hz, f.w - hw);
}
__device__ __forceinline__ void mma16816(float* d, const uint32_t* a,
                                         uint32_t b0, uint32_t b1) {
    asm volatile(
        "mma.sync.aligned.m16n8k16.row.col.f32.bf16.bf16.f32 "
        "{%0,%1,%2,%3},{%4,%5,%6,%7},{%8,%9},{%0,%1,%2,%3};"
        : "+f"(d[0]), "+f"(d[1]), "+f"(d[2]), "+f"(d[3])
        : "r"(a[0]), "r"(a[1]), "r"(a[2]), "r"(a[3]), "r"(b0), "r"(b1));
}

__global__ void __launch_bounds__(128) k_big_mma(const float* __restrict__ Wz,
                                                 float* __restrict__ out) {
    __shared__ uint32_t sAh[2][64*PITCH];
    __shared__ uint32_t sAl[2][64*PITCH];
    __shared__ uint32_t sWh[2][32*PITCH];
    __shared__ uint32_t sWl[2][32*PITCH];
    const int t    = threadIdx.x;
    const int lane = t & 31;
    const int wid  = t >> 5;
    const int wb   = wid >> 1;        // b-half: rows 32*wb..
    const int wl   = wid & 1;         // l-half: cols 16*wl..
    const int g    = lane >> 2;       // 0..7
    const int t4   = lane & 3;        // 0..3
    const int l0   = blockIdx.x * 32;

    float4 av[4], wv[2];
    auto ldg = [&](int c) {
        #pragma unroll
        for (int r = 0; r < 4; r++) {
            int id = t + 128*r;                 // 0..511
            int row = id >> 3, c4 = id & 7;     // A: 64 rows x 8 f4
            av[r] = *(const float4*)(g_zz2 + row*Dd + c*32 + 4*c4);
        }
        #pragma unroll
        for (int r = 0; r < 2; r++) {
            int id = t + 128*r;                 // 0..255
            int row = id >> 3, c4 = id & 7;     // W: 32 rows x 8 f4
            wv[r] = *(const float4*)(Wz + (l0 + row)*Dd + c*32 + 4*c4);
        }
    };
    auto sts = [&](int buf) {
        #pragma unroll
        for (int r = 0; r < 4; r++) {
            int id = t + 128*r;
            int row = id >> 3, c4 = id & 7;
            uint32_t h0, h1, q0, q1;
            cvt_hilo(av[r], h0, h1, q0, q1);
            int idx = row*PITCH + 2*c4;
            *(uint2*)&sAh[buf][idx] = make_uint2(h0, h1);
            *(uint2*)&sAl[buf][idx] = make_uint2(q0, q1);
        }
        #pragma unroll
        for (int r = 0; r < 2; r++) {
            int id = t + 128*r;
            int row = id >> 3, c4 = id & 7;
            uint32_t h0, h1, q0, q1;
            cvt_hilo(wv[r], h0, h1, q0, q1);
            int idx = row*PITCH + 2*c4;
            *(uint2*)&sWh[buf][idx] = make_uint2(h0, h1);
            *(uint2*)&sWl[buf][idx] = make_uint2(q0, q1);
        }
    };

    float D[2][2][4];
    #pragma unroll
    for (int i = 0; i < 2; i++)
        #pragma unroll
        for (int j = 0; j < 2; j++)
            #pragma unroll
            for (int r = 0; r < 4; r++) D[i][j][r] = 0.f;

    ldg(0);
    #pragma unroll 1
    for (int c = 0; c < 16; c++) {
        const int cur = c & 1;
        sts(cur);
        __syncthreads();                 // cur tiles visible to all warps
        if (c < 15) ldg(c + 1);          // prefetch next chunk into regs
        const uint32_t* Ah = sAh[cur];
        const uint32_t* Al = sAl[cur];
        const uint32_t* Wh = sWh[cur];
        const uint32_t* Wl = sWl[cur];
        #pragma unroll
        for (int s = 0; s < 2; s++) {    // two k16 steps per 32k chunk
            const int kc = 8*s + t4;
            uint32_t bh[2][2], bl[2][2];
            #pragma unroll
            for (int j = 0; j < 2; j++) {
                int rw = (16*wl + 8*j + g)*PITCH;
                bh[j][0] = Wh[rw + kc];     bh[j][1] = Wh[rw + kc + 4];
                bl[j][0] = Wl[rw + kc];     bl[j][1] = Wl[rw + kc + 4];
            }
            #pragma unroll
            for (int i = 0; i < 2; i++) {
                int r0 = (32*wb + 16*i + g)*PITCH;
                int r1 = r0 + 8*PITCH;
                uint32_t ah[4], al[4];
                ah[0] = Ah[r0 + kc];  ah[1] = Ah[r1 + kc];
                ah[2] = Ah[r0 + kc + 4]; ah[3] = Ah[r1 + kc + 4];
                al[0] = Al[r0 + kc];  al[1] = Al[r1 + kc];
                al[2] = Al[r0 + kc + 4]; al[3] = Al[r1 + kc + 4];
                #pragma unroll
                for (int j = 0; j < 2; j++) {
                    mma16816(D[i][j], ah, bh[j][0], bh[j][1]);   // Ah*Wh
                    mma16816(D[i][j], ah, bl[j][0], bl[j][1]);   // Ah*Wl
                    mma16816(D[i][j], al, bh[j][0], bh[j][1]);   // Al*Wh
                }
            }
        }
        __syncthreads();                 // done reading cur before overwrite
    }

    // epilogue: scale by s[b], store float2 (cols 2t4, 2t4+1 contiguous)
    #pragma unroll
    for (int i = 0; i < 2; i++) {
        const int b0r = 32*wb + 16*i + g;
        const float s0 = g_s_pad[b0r*32];
        const float s1 = g_s_pad[(b0r + 8)*32];
        #pragma unroll
        for (int j = 0; j < 2; j++) {
            const int lc = l0 + 16*wl + 8*j + 2*t4;
            *(float2*)(out + b0r*Ll + lc)     = make_float2(D[i][j][0]*s0, D[i][j][1]*s0);
            *(float2*)(out + (b0r+8)*Ll + lc) = make_float2(D[i][j][2]*s1, D[i][j][3]*s1);
        }
    }
}

extern "C" void kernel_launch(void* const* d_in, const int* in_sizes, int n_in,
                              void* d_out, int out_size) {
    const float* z      = (const float*)d_in[0];
    const int*   y      = (const int*)  d_in[1];
    const float* W_yemb = (const float*)d_in[2];
    const float* b_yemb = (const float*)d_in[3];
    const float* Wy1    = (const float*)d_in[4];
    const float* by1    = (const float*)d_in[5];
    const float* Wy2    = (const float*)d_in[6];
    const float* by2    = (const float*)d_in[7];
    const float* Wz1    = (const float*)d_in[8];
    const float* bz1    = (const float*)d_in[9];
    const float* Wz2    = (const float*)d_in[10];
    const float* bz2    = (const float*)d_in[11];
    const float* W_zlat = (const float*)d_in[12];
    const float* w_proj = (const float*)d_in[13];
    float* out = (float*)d_out;

    k_prep<<<dim3(Bsz, 4), 128>>>(z, y, W_yemb, b_yemb, by1, bz1);
    k_small<1><<<dim3(128, 2), 256>>>(z, Wy1, Wz1, nullptr, nullptr, nullptr);
    k_small<2><<<dim3(128, 2), 256>>>(z, Wy2, Wz2, by2, bz2, w_proj);
    k_big_mma<<<Ll/32, 128>>>(W_zlat, out);
}